// round 9
// baseline (speedup 1.0000x reference)
#include <cuda_runtime.h>
#include <math.h>
#include <stdint.h>

// Problem constants
#define BATCH   8
#define DIM     1024
#define HW      1024
#define NROW    8192
#define NCODE   8192
#define ZQ_ELEMS (BATCH*DIM*HW)
#define OFF_LOSS  ZQ_ELEMS
#define OFF_PERP  (ZQ_ELEMS + 1)
#define OFF_IDX   (ZQ_ELEMS + 2)

#define NTILES 64
#define KSLOT  8

// ---------------- device scratch ---------------------------------------------
__device__ float   g_zflat[(size_t)NROW * DIM];
__device__ int8_t  g_zq[(size_t)NROW * DIM];
__device__ int8_t  g_eq[(size_t)NCODE * DIM];
__device__ float   g_S[NROW];
__device__ float   g_T[NCODE];
__device__ float   g_szs[NROW];      // z row dequant scale (max/127)
__device__ float   g_saz[NROW];      // z row sum|z|
__device__ float   g_ses[NCODE];     // e row dequant scale
__device__ float   g_margin[NROW];
__device__ unsigned g_semax_bits;    // max e scale (float bits)
__device__ unsigned g_saemax_bits;   // max sum|e| (float bits)
__device__ float   g_tmin[(size_t)NROW * NTILES];
__device__ int     g_tcnt[(size_t)NROW * NTILES];
__device__ unsigned long long g_tcand[(size_t)NROW * NTILES * KSLOT];
__device__ int     g_idx[NROW];
__device__ int     g_hist[NCODE];
__device__ double  g_loss;

// ---------------- PTX helpers -------------------------------------------------
__device__ __forceinline__ uint32_t smem_u32(const void* p) {
    uint32_t a;
    asm("{ .reg .u64 t; cvta.to.shared.u64 t, %1; cvt.u32.u64 %0, t; }" : "=r"(a) : "l"(p));
    return a;
}
__device__ __forceinline__ void cp_async16(uint32_t saddr, const void* gptr) {
    asm volatile("cp.async.cg.shared.global [%0], [%1], 16;" :: "r"(saddr), "l"(gptr));
}
__device__ __forceinline__ void cp_commit() { asm volatile("cp.async.commit_group;" ::: "memory"); }
__device__ __forceinline__ void cp_wait0()  { asm volatile("cp.async.wait_group 0;" ::: "memory"); }

__device__ __forceinline__ void ldsm_x4(uint32_t* r, uint32_t addr) {
    asm volatile("ldmatrix.sync.aligned.m8n8.x4.shared.b16 {%0,%1,%2,%3}, [%4];"
                 : "=r"(r[0]), "=r"(r[1]), "=r"(r[2]), "=r"(r[3]) : "r"(addr));
}
__device__ __forceinline__ void imma16832(int* d, const uint32_t* a, uint32_t b0, uint32_t b1) {
    asm volatile("mma.sync.aligned.m16n8k32.row.col.s32.s8.s8.s32 "
                 "{%0,%1,%2,%3}, {%4,%5,%6,%7}, {%8,%9}, {%0,%1,%2,%3};"
                 : "+r"(d[0]), "+r"(d[1]), "+r"(d[2]), "+r"(d[3])
                 : "r"(a[0]), "r"(a[1]), "r"(a[2]), "r"(a[3]), "r"(b0), "r"(b1));
}
__device__ __forceinline__ unsigned long long packvc(float v, int code) {
    return ((unsigned long long)__float_as_uint(v) << 32) | (unsigned)code;
}
__device__ __forceinline__ float unpackv(unsigned long long p) {
    return __uint_as_float((unsigned)(p >> 32));
}
__device__ __forceinline__ void atomicMaxFloat(unsigned* addr, float v) {
    atomicMax(addr, __float_as_uint(v));   // valid: all values >= 0
}

// ---------------- kernel 0: zero accumulators --------------------------------
__global__ void vq_zero_kernel() {
    int t = blockIdx.x * blockDim.x + threadIdx.x;
    if (t < NCODE) g_hist[t] = 0;
    if (t == 0) { g_loss = 0.0; g_semax_bits = 0u; g_saemax_bits = 0u; }
}

// ---------------- kernel 1: transpose z -> zflat (fp32) ----------------------
__global__ void vq_transpose_kernel(const float* __restrict__ z) {
    __shared__ float tile[32][33];
    int b = blockIdx.z;
    int hw0 = blockIdx.x * 32;
    int c0  = blockIdx.y * 32;
    const float* src = z + ((size_t)b << 20);
    float* dst = g_zflat + ((size_t)b << 20);
    #pragma unroll
    for (int r = threadIdx.y; r < 32; r += 8)
        tile[r][threadIdx.x] = src[(size_t)(c0 + r) * HW + hw0 + threadIdx.x];
    __syncthreads();
    #pragma unroll
    for (int r = threadIdx.y; r < 32; r += 8)
        dst[(size_t)(hw0 + r) * DIM + c0 + threadIdx.x] = tile[threadIdx.x][r];
}

// ---------------- kernel 2: row stats + int8 quantization --------------------
// One warp per row (z rows then e rows): S=sum v^2, SA=sum|v|, mx=max|v|,
// then quantize row to int8 with scale mx/127.
__global__ void vq_rowsum_kernel(const float* __restrict__ emb) {
    int gw   = (blockIdx.x * blockDim.x + threadIdx.x) >> 5;
    int lane = threadIdx.x & 31;
    if (gw >= NROW + NCODE) return;
    bool isEmb = (gw >= NROW);
    int row = isEmb ? (gw - NROW) : gw;
    const float4* s4 = isEmb ? (const float4*)(emb + (size_t)row * DIM)
                             : (const float4*)(g_zflat + (size_t)row * DIM);
    uint32_t* q4 = isEmb ? (uint32_t*)(g_eq + (size_t)row * DIM)
                         : (uint32_t*)(g_zq + (size_t)row * DIM);
    float4 v[8];
    float s2 = 0.f, sa = 0.f, mx = 0.f;
    #pragma unroll
    for (int j = 0; j < 8; j++) {
        v[j] = s4[lane + 32 * j];
        s2 += v[j].x * v[j].x + v[j].y * v[j].y + v[j].z * v[j].z + v[j].w * v[j].w;
        sa += fabsf(v[j].x) + fabsf(v[j].y) + fabsf(v[j].z) + fabsf(v[j].w);
        mx = fmaxf(mx, fmaxf(fmaxf(fabsf(v[j].x), fabsf(v[j].y)),
                             fmaxf(fabsf(v[j].z), fabsf(v[j].w))));
    }
    #pragma unroll
    for (int o = 16; o; o >>= 1) {
        s2 += __shfl_xor_sync(0xffffffffu, s2, o);
        sa += __shfl_xor_sync(0xffffffffu, sa, o);
        mx  = fmaxf(mx, __shfl_xor_sync(0xffffffffu, mx, o));
    }
    float inv = 127.0f / mx;
    #pragma unroll
    for (int j = 0; j < 8; j++) {
        int q0 = __float2int_rn(v[j].x * inv);
        int q1 = __float2int_rn(v[j].y * inv);
        int q2 = __float2int_rn(v[j].z * inv);
        int q3 = __float2int_rn(v[j].w * inv);
        q4[lane + 32 * j] = (uint32_t)(q0 & 255) | ((uint32_t)(q1 & 255) << 8)
                          | ((uint32_t)(q2 & 255) << 16) | ((uint32_t)(q3 & 255) << 24);
    }
    if (lane == 0) {
        float sc = mx * (1.0f / 127.0f);
        if (!isEmb) { g_S[row] = s2; g_szs[row] = sc; g_saz[row] = sa; }
        else {
            g_T[row] = s2; g_ses[row] = sc;
            atomicMaxFloat(&g_semax_bits, sc);
            atomicMaxFloat(&g_saemax_bits, sa);
        }
    }
}

// ---------------- kernel 2b: per-row rigorous margin -------------------------
__global__ void vq_margin_kernel() {
    int n = blockIdx.x * blockDim.x + threadIdx.x;
    if (n >= NROW) return;
    float seM  = __uint_as_float(g_semax_bits);
    float saeM = __uint_as_float(g_saemax_bits);
    float sz = g_szs[n], saz = g_saz[n];
    // |v - d| <= m/2 worst case:  quant error on 2P + fp rounding slop
    float m = 2.0f * (saeM * 0.5f * sz + saz * 0.5f * seM
                      + 1024.0f * 0.25f * sz * seM) + 4e-4f;
    g_margin[n] = m;
}

// ---------------- kernel 3: int8 IMMA GEMM + fused candidate epilogue --------
// CTA: 128 z rows x 128 codes, BK=64 (64B/row int8), 256 thr (8 warps 2x4,
// warp 64x32). 2 stages, R3-proven schedule. Exact s32 accumulation.
#define ASTRIDE 80u
#define STAGE_BYTES 20480u
#define B_OFF 10240u

__global__ __launch_bounds__(256, 2)
void vq_mm_kernel() {
    __shared__ __align__(128) uint8_t smem[2 * STAGE_BYTES];
    const uint32_t sb = smem_u32(smem);
    const int tid = threadIdx.x;
    const int lane = tid & 31, wid = tid >> 5;
    const int warpM = wid >> 2, warpN = wid & 3;
    const int rowBase  = blockIdx.y * 128;
    const int codeBase = blockIdx.x * 128;
    const int tileN = blockIdx.x;

    // loader: t<128 -> A row t; else B row t-128. 64B per row per stage.
    const int lr = tid & 127;
    const bool isB = tid >= 128;
    const int8_t* gsrc = isB ? (g_eq + (size_t)(codeBase + lr) * DIM)
                             : (g_zq + (size_t)(rowBase + lr) * DIM);
    const uint32_t st = (isB ? B_OFF : 0u) + (uint32_t)lr * ASTRIDE;

    // ldmatrix addressing (16-row blocks, 16B column select per lane group)
    const uint32_t a_base = (uint32_t)((warpM * 64 + (lane & 15)) * ASTRIDE + (lane >> 4) * 16);
    const uint32_t b_base = B_OFF + (uint32_t)((warpN * 32 + (lane & 15)) * ASTRIDE + (lane >> 4) * 16);

    int acc[4][4][4];
    #pragma unroll
    for (int i = 0; i < 4; i++)
        #pragma unroll
        for (int j = 0; j < 4; j++)
            #pragma unroll
            for (int k = 0; k < 4; k++) acc[i][j][k] = 0;

    // prefetch stage 0
    {
        uint32_t a0 = sb + st;
        #pragma unroll
        for (int c = 0; c < 4; c++) cp_async16(a0 + c * 16u, gsrc + c * 16);
        cp_commit();
    }

    #pragma unroll 1
    for (int kt = 0; kt < 16; kt++) {
        cp_wait0();
        __syncthreads();
        if (kt < 15) {
            uint32_t a0 = sb + (uint32_t)((kt + 1) & 1) * STAGE_BYTES + st;
            const int8_t* g = gsrc + (kt + 1) * 64;
            #pragma unroll
            for (int c = 0; c < 4; c++) cp_async16(a0 + c * 16u, g + c * 16);
            cp_commit();
        }
        const uint32_t As0 = sb + (uint32_t)(kt & 1) * STAGE_BYTES + a_base;
        const uint32_t Bs0 = sb + (uint32_t)(kt & 1) * STAGE_BYTES + b_base;
        #pragma unroll
        for (int ks = 0; ks < 2; ks++) {
            uint32_t a[4][4], b[2][4];
            #pragma unroll
            for (int mt = 0; mt < 4; mt++) ldsm_x4(a[mt], As0 + mt * (16u * ASTRIDE) + ks * 32u);
            #pragma unroll
            for (int pr = 0; pr < 2; pr++)  ldsm_x4(b[pr], Bs0 + pr * (16u * ASTRIDE) + ks * 32u);
            #pragma unroll
            for (int mt = 0; mt < 4; mt++)
                #pragma unroll
                for (int nt = 0; nt < 4; nt++)
                    imma16832(acc[mt][nt], a[mt],
                              b[nt >> 1][nt & 1], b[nt >> 1][(nt & 1) + 2]);
        }
    }
    __syncthreads();

    // ---- epilogue: dequant, per-row tile min + margin candidates ----
    unsigned* sMin = (unsigned*)smem;                               // 128 * 4B (float bits)
    int* sCnt = (int*)(smem + 512);                                 // 128 * 4B
    unsigned long long* sCand = (unsigned long long*)(smem + 1024); // 128 * 8 * 8B

    for (int i = tid; i < 128; i += 256) { sMin[i] = 0x7f800000u; sCnt[i] = 0; }
    __syncthreads();

    float Sv[4][2], szr[4][2], mr[4][2], Tv[4][2], te[4][2];
    #pragma unroll
    for (int mt = 0; mt < 4; mt++) {
        int r0 = rowBase + warpM * 64 + mt * 16 + (lane >> 2);
        Sv[mt][0] = g_S[r0];   Sv[mt][1] = g_S[r0 + 8];
        szr[mt][0] = g_szs[r0]; szr[mt][1] = g_szs[r0 + 8];
        mr[mt][0] = g_margin[r0]; mr[mt][1] = g_margin[r0 + 8];
    }
    #pragma unroll
    for (int nt = 0; nt < 4; nt++) {
        int c0 = codeBase + warpN * 32 + nt * 8 + (lane & 3) * 2;
        Tv[nt][0] = g_T[c0];   Tv[nt][1] = g_T[c0 + 1];
        te[nt][0] = 2.0f * g_ses[c0]; te[nt][1] = 2.0f * g_ses[c0 + 1];
    }

    // convert acc -> coarse v (in fp32), in place
    float vv[4][4][4];
    #pragma unroll
    for (int mt = 0; mt < 4; mt++)
        #pragma unroll
        for (int half = 0; half < 2; half++)
            #pragma unroll
            for (int nt = 0; nt < 4; nt++)
                #pragma unroll
                for (int j = 0; j < 2; j++) {
                    float Q = __fadd_rn(Sv[mt][half], Tv[nt][j]);
                    float scale = szr[mt][half] * te[nt][j];
                    vv[mt][nt][half * 2 + j] =
                        __fsub_rn(Q, scale * (float)acc[mt][nt][half * 2 + j]);
                }

    // pass 1: per-row min
    #pragma unroll
    for (int mt = 0; mt < 4; mt++) {
        #pragma unroll
        for (int half = 0; half < 2; half++) {
            float mn = vv[mt][0][half * 2];
            #pragma unroll
            for (int nt = 0; nt < 4; nt++)
                #pragma unroll
                for (int j = 0; j < 2; j++)
                    mn = fminf(mn, vv[mt][nt][half * 2 + j]);
            mn = fminf(mn, __shfl_xor_sync(0xffffffffu, mn, 1));
            mn = fminf(mn, __shfl_xor_sync(0xffffffffu, mn, 2));
            if ((lane & 3) == 0) {
                int rl = warpM * 64 + mt * 16 + (lane >> 2) + half * 8;
                atomicMin(&sMin[rl], __float_as_uint(mn));  // positive floats
            }
        }
    }
    __syncthreads();

    // pass 2: append candidates within tileMin + margin(row)
    #pragma unroll
    for (int mt = 0; mt < 4; mt++) {
        #pragma unroll
        for (int half = 0; half < 2; half++) {
            int rl = warpM * 64 + mt * 16 + (lane >> 2) + half * 8;
            float thr = __uint_as_float(sMin[rl]) + mr[mt][half];
            #pragma unroll
            for (int nt = 0; nt < 4; nt++) {
                int c0 = warpN * 32 + nt * 8 + (lane & 3) * 2;
                #pragma unroll
                for (int j = 0; j < 2; j++) {
                    float v = vv[mt][nt][half * 2 + j];
                    if (v <= thr) {
                        int p = atomicAdd(&sCnt[rl], 1);
                        if (p < KSLOT) sCand[rl * KSLOT + p] = packvc(v, codeBase + c0 + j);
                    }
                }
            }
        }
    }
    __syncthreads();

    // write out
    if (tid < 128) {
        size_t o = (size_t)(rowBase + tid) * NTILES + tileN;
        g_tmin[o] = __uint_as_float(sMin[tid]);
        g_tcnt[o] = sCnt[tid];
    }
    {
        int row = tid >> 1, h = (tid & 1) * 4;
        size_t o = ((size_t)(rowBase + row) * NTILES + tileN) * KSLOT + h;
        #pragma unroll
        for (int j = 0; j < 4; j++) g_tcand[o + j] = sCand[row * KSLOT + h + j];
    }
}

// ---------------- kernel 4: parallel candidate gather + exact fp32 rescore ---
__global__ __launch_bounds__(256, 4)
void vq_scan_kernel(const float* __restrict__ emb, float* __restrict__ out) {
    const int n = blockIdx.x;
    const int t = threadIdx.x;
    const int lane = t & 31, w = t >> 5;

    __shared__ float s_tm[NTILES];
    __shared__ int   s_tc[NTILES];
    __shared__ float s_thr;
    __shared__ int   s_cnt;
    __shared__ int   s_codes[512];
    __shared__ int   s_ovf[16];
    __shared__ int   s_novf;
    __shared__ float s_ws[8];
    __shared__ float s_bd;
    __shared__ int   s_bk;

    if (t < NTILES) {
        s_tm[t] = g_tmin[(size_t)n * NTILES + t];
        s_tc[t] = g_tcnt[(size_t)n * NTILES + t];
    }
    if (t == 0) {
        s_cnt = 0; s_novf = 0;
        s_bd = __int_as_float(0x7f800000);
        s_bk = 0x7fffffff;
    }
    __syncthreads();

    if (t < 32) {
        float m = fminf(s_tm[t], s_tm[t + 32]);
        #pragma unroll
        for (int o = 16; o; o >>= 1) m = fminf(m, __shfl_down_sync(0xffffffffu, m, o));
        if (t == 0) s_thr = m + g_margin[n];
    }
    __syncthreads();
    const float thr = s_thr;

    if (t < NTILES && s_tm[t] <= thr) {
        int cnt = s_tc[t];
        if (cnt <= KSLOT) {
            size_t base = ((size_t)n * NTILES + t) * KSLOT;
            for (int c = 0; c < cnt; c++) {
                unsigned long long cd = g_tcand[base + c];
                if (unpackv(cd) <= thr) {
                    int p = atomicAdd(&s_cnt, 1);
                    if (p < 512) s_codes[p] = (int)(cd & 0xffffffffu);
                }
            }
        } else {
            int p = atomicAdd(&s_novf, 1);
            if (p < 16) s_ovf[p] = t;
        }
    }
    __syncthreads();
    {
        int novf = s_novf < 16 ? s_novf : 16;
        for (int o = 0; o < novf; o++) {
            if (t < 128) {
                int p = atomicAdd(&s_cnt, 1);
                if (p < 512) s_codes[p] = s_ovf[o] * 128 + t;
            }
        }
    }
    __syncthreads();

    const bool full = (s_cnt > 512) || (s_novf > 16);
    const int total = full ? NCODE : s_cnt;

    const float4 zv = ((const float4*)(g_zflat + (size_t)n * DIM))[t];
    const float S = g_S[n];

    for (int c = 0; c < total; c++) {
        int k = full ? c : s_codes[c];
        float4 ev = ((const float4*)(emb + (size_t)k * DIM))[t];
        float p = fmaf(zv.x, ev.x, fmaf(zv.y, ev.y, fmaf(zv.z, ev.z, zv.w * ev.w)));
        #pragma unroll
        for (int o = 16; o; o >>= 1) p += __shfl_down_sync(0xffffffffu, p, o);
        if (lane == 0) s_ws[w] = p;
        __syncthreads();
        if (t == 0) {
            float P = 0.f;
            #pragma unroll
            for (int i = 0; i < 8; i++) P += s_ws[i];
            float T = g_T[k];
            float d = __fsub_rn(__fadd_rn(S, T), 2.0f * P);
            if (d < s_bd || (d == s_bd && k < s_bk)) { s_bd = d; s_bk = k; }
        }
        __syncthreads();
    }
    if (t == 0) {
        int bk = s_bk;
        g_idx[n] = bk;
        out[OFF_IDX + n] = (float)bk;
        atomicAdd(&g_hist[bk], 1);
    }
}

// ---------------- kernel 5: gather codebook, STE output, loss ----------------
__global__ void vq_gather_kernel(const float* __restrict__ z,
                                 const float* __restrict__ emb,
                                 float* __restrict__ out) {
    int t = blockIdx.x * blockDim.x + threadIdx.x;
    int hw = t & 1023;
    int c  = (t >> 10) & 1023;
    int b  = t >> 20;
    int n  = (b << 10) | hw;
    int code = g_idx[n];
    float zv = z[t];
    float e  = emb[(size_t)code * DIM + c];
    float diff = __fsub_rn(e, zv);
    out[t] = __fadd_rn(zv, diff);
    float sq = diff * diff;
    #pragma unroll
    for (int o = 16; o; o >>= 1) sq += __shfl_down_sync(0xffffffffu, sq, o);
    __shared__ float warpsum[8];
    int lane = threadIdx.x & 31, wid = threadIdx.x >> 5;
    if (lane == 0) warpsum[wid] = sq;
    __syncthreads();
    if (wid == 0) {
        float v = (lane < 8) ? warpsum[lane] : 0.f;
        #pragma unroll
        for (int o = 4; o; o >>= 1) v += __shfl_down_sync(0xffffffffu, v, o);
        if (lane == 0) atomicAdd(&g_loss, (double)v);
    }
}

// ---------------- kernel 6: finalize loss + perplexity -----------------------
__global__ void vq_finalize_kernel(float* __restrict__ out) {
    __shared__ float warpsum[8];
    int tid = threadIdx.x;
    float s = 0.f;
    for (int k = tid; k < NCODE; k += 256) {
        float c = (float)g_hist[k];
        float p = c * (1.0f / (float)NROW);
        s += p * logf(p + 1e-10f);
    }
    #pragma unroll
    for (int o = 16; o; o >>= 1) s += __shfl_down_sync(0xffffffffu, s, o);
    int lane = tid & 31, wid = tid >> 5;
    if (lane == 0) warpsum[wid] = s;
    __syncthreads();
    if (wid == 0) {
        float v = (lane < 8) ? warpsum[lane] : 0.f;
        #pragma unroll
        for (int o = 4; o; o >>= 1) v += __shfl_down_sync(0xffffffffu, v, o);
        if (lane == 0) {
            out[OFF_PERP] = expf(-v);
            double m = g_loss / (double)ZQ_ELEMS;
            float mf = (float)m;
            out[OFF_LOSS] = __fadd_rn(mf, 0.25f * mf);
        }
    }
}

// ---------------- launch ------------------------------------------------------
extern "C" void kernel_launch(void* const* d_in, const int* in_sizes, int n_in,
                              void* d_out, int out_size) {
    const float* z   = (const float*)d_in[0];
    const float* emb = (const float*)d_in[1];
    float* out = (float*)d_out;
    (void)in_sizes; (void)n_in; (void)out_size;

    vq_zero_kernel<<<32, 256>>>();

    dim3 tb(32, 8);
    dim3 tg(32, 32, BATCH);
    vq_transpose_kernel<<<tg, tb>>>(z);

    vq_rowsum_kernel<<<(NROW + NCODE) * 32 / 256, 256>>>(emb);

    vq_margin_kernel<<<NROW / 256, 256>>>();

    dim3 mg(NCODE / 128, NROW / 128);
    vq_mm_kernel<<<mg, 256>>>();

    vq_scan_kernel<<<NROW, 256>>>(emb, out);

    vq_gather_kernel<<<ZQ_ELEMS / 256, 256>>>(z, emb, out);

    vq_finalize_kernel<<<1, 256>>>(out);
}

// round 10
// speedup vs baseline: 3.3861x; 3.3861x over previous
#include <cuda_runtime.h>
#include <cuda_fp16.h>
#include <math.h>
#include <stdint.h>

// Problem constants
#define BATCH   8
#define DIM     1024
#define HW      1024
#define NROW    8192
#define NCODE   8192
#define ZQ_ELEMS (BATCH*DIM*HW)
#define OFF_LOSS  ZQ_ELEMS
#define OFF_PERP  (ZQ_ELEMS + 1)
#define OFF_IDX   (ZQ_ELEMS + 2)

#define ESCALE 512.0f
#define MARGIN 1e-3f
#define NTILES 64
#define KSLOT  8

// ---------------- device scratch ---------------------------------------------
__device__ float   g_zflat[(size_t)NROW * DIM];
__device__ __half  g_zh[(size_t)NROW * DIM];
__device__ __half  g_eh[(size_t)NCODE * DIM];
__device__ float   g_S[NROW];
__device__ float   g_T[NCODE];
__device__ float   g_tmin[(size_t)NROW * NTILES];
__device__ int     g_tcnt[(size_t)NROW * NTILES];
__device__ unsigned long long g_tcand[(size_t)NROW * NTILES * KSLOT];
__device__ int     g_idx[NROW];
__device__ int     g_hist[NCODE];
__device__ double  g_loss;

// ---------------- PTX helpers -------------------------------------------------
__device__ __forceinline__ uint32_t smem_u32(const void* p) {
    uint32_t a;
    asm("{ .reg .u64 t; cvta.to.shared.u64 t, %1; cvt.u32.u64 %0, t; }" : "=r"(a) : "l"(p));
    return a;
}
__device__ __forceinline__ void cp_async16(uint32_t saddr, const void* gptr) {
    asm volatile("cp.async.cg.shared.global [%0], [%1], 16;" :: "r"(saddr), "l"(gptr));
}
__device__ __forceinline__ void cp_commit() { asm volatile("cp.async.commit_group;" ::: "memory"); }
__device__ __forceinline__ void cp_wait0()  { asm volatile("cp.async.wait_group 0;" ::: "memory"); }

__device__ __forceinline__ void ldsm_x4(uint32_t* r, uint32_t addr) {
    asm volatile("ldmatrix.sync.aligned.m8n8.x4.shared.b16 {%0,%1,%2,%3}, [%4];"
                 : "=r"(r[0]), "=r"(r[1]), "=r"(r[2]), "=r"(r[3]) : "r"(addr));
}
__device__ __forceinline__ void mma16816(float* d, const uint32_t* a, uint32_t b0, uint32_t b1) {
    asm volatile("mma.sync.aligned.m16n8k16.row.col.f32.f16.f16.f32 "
                 "{%0,%1,%2,%3}, {%4,%5,%6,%7}, {%8,%9}, {%0,%1,%2,%3};"
                 : "+f"(d[0]), "+f"(d[1]), "+f"(d[2]), "+f"(d[3])
                 : "r"(a[0]), "r"(a[1]), "r"(a[2]), "r"(a[3]), "r"(b0), "r"(b1));
}
__device__ __forceinline__ unsigned long long packvc(float v, int code) {
    return ((unsigned long long)__float_as_uint(v) << 32) | (unsigned)code;
}
__device__ __forceinline__ float unpackv(unsigned long long p) {
    return __uint_as_float((unsigned)(p >> 32));
}

// ---------------- kernel 0: zero accumulators --------------------------------
__global__ void vq_zero_kernel() {
    int t = blockIdx.x * blockDim.x + threadIdx.x;
    if (t < NCODE) g_hist[t] = 0;
    if (t == 0) g_loss = 0.0;
}

// ---------------- kernel 1: transpose z -> zflat (fp32 + fp16) ---------------
__global__ void vq_transpose_kernel(const float* __restrict__ z) {
    __shared__ float tile[32][33];
    int b = blockIdx.z;
    int hw0 = blockIdx.x * 32;
    int c0  = blockIdx.y * 32;
    const float* src = z + ((size_t)b << 20);
    float* dst = g_zflat + ((size_t)b << 20);
    __half* dsth = g_zh + ((size_t)b << 20);
    #pragma unroll
    for (int r = threadIdx.y; r < 32; r += 8)
        tile[r][threadIdx.x] = src[(size_t)(c0 + r) * HW + hw0 + threadIdx.x];
    __syncthreads();
    #pragma unroll
    for (int r = threadIdx.y; r < 32; r += 8) {
        float v = tile[threadIdx.x][r];
        size_t o = (size_t)(hw0 + r) * DIM + c0 + threadIdx.x;
        dst[o]  = v;
        dsth[o] = __float2half_rn(v);
    }
}

// ---------------- kernel 2: row norms + emb fp16 (scaled) conversion ---------
__global__ void vq_rowsum_kernel(const float* __restrict__ emb) {
    int gw   = (blockIdx.x * blockDim.x + threadIdx.x) >> 5;
    int lane = threadIdx.x & 31;
    if (gw >= NROW + NCODE) return;
    const float* src;
    float* dst;
    bool isEmb = (gw >= NROW);
    if (!isEmb) { src = g_zflat + (size_t)gw * DIM; dst = g_S + gw; }
    else        { src = emb + (size_t)(gw - NROW) * DIM; dst = g_T + (gw - NROW); }
    const float4* s4 = (const float4*)src;
    __half2* eh2 = isEmb ? (__half2*)(g_eh + (size_t)(gw - NROW) * DIM) : nullptr;
    float acc = 0.f;
    #pragma unroll 4
    for (int i = lane; i < DIM / 4; i += 32) {
        float4 v = s4[i];
        if (isEmb) {
            eh2[i * 2]     = __floats2half2_rn(v.x * ESCALE, v.y * ESCALE);
            eh2[i * 2 + 1] = __floats2half2_rn(v.z * ESCALE, v.w * ESCALE);
        }
        acc += v.x * v.x + v.y * v.y + v.z * v.z + v.w * v.w;
    }
    #pragma unroll
    for (int o = 16; o; o >>= 1) acc += __shfl_down_sync(0xffffffffu, acc, o);
    if (lane == 0) *dst = acc;
}

// ---------------- kernel 3: fp16 HMMA GEMM (R3 mainloop) + lean epilogue -----
// CTA: 128 z rows x 128 codes, BK=32, 256 threads (8 warps 2x4, warp 64x32).
// 2-stage cp.async double buffer (the proven 497us schedule).
#define AS_OFF(s) ((s) * 10240u)
#define BS_OFF(s) (20480u + (s) * 10240u)

__global__ __launch_bounds__(256, 2)
void vq_mm_kernel() {
    __shared__ __align__(128) uint8_t smem[40960];
    const uint32_t sb = smem_u32(smem);
    const int tid = threadIdx.x;
    const int lane = tid & 31, wid = tid >> 5;
    const int warpM = wid >> 2, warpN = wid & 3;
    const int rowBase  = blockIdx.y * 128;
    const int codeBase = blockIdx.x * 128;
    const int tileN = blockIdx.x;

    // cp.async task: row = tid>>1, chunks (tid&1)*2 + {0,1}
    const int ldrow = tid >> 1;
    const int ldc0  = (tid & 1) * 2;
    const __half* gA = g_zh + (size_t)(rowBase + ldrow) * DIM + ldc0 * 8;
    const __half* gB = g_eh + (size_t)(codeBase + ldrow) * DIM + ldc0 * 8;
    const uint32_t stA = (uint32_t)ldrow * 80u + (uint32_t)ldc0 * 16u;

    // ldmatrix lane addressing
    const uint32_t a_base = (uint32_t)((warpM * 64 + (lane & 15)) * 80 + ((lane >> 4) * 8) * 2);
    const int grp = lane >> 3;
    const uint32_t b_base = (uint32_t)((warpN * 32 + ((grp >> 1) * 8) + (lane & 7)) * 80
                                       + ((grp & 1) * 8) * 2);

    float acc[4][4][4];
    #pragma unroll
    for (int i = 0; i < 4; i++)
        #pragma unroll
        for (int j = 0; j < 4; j++)
            #pragma unroll
            for (int k = 0; k < 4; k++) acc[i][j][k] = 0.f;

    // prefetch stage 0
    {
        uint32_t a0 = sb + AS_OFF(0) + stA;
        cp_async16(a0,      gA);
        cp_async16(a0 + 16, gA + 8);
        uint32_t b0 = sb + BS_OFF(0) + stA;
        cp_async16(b0,      gB);
        cp_async16(b0 + 16, gB + 8);
        cp_commit();
    }

    #pragma unroll 1
    for (int kt = 0; kt < 32; kt++) {
        cp_wait0();
        __syncthreads();
        if (kt < 31) {
            int k0 = (kt + 1) * 32;
            int s  = (kt + 1) & 1;
            uint32_t a0 = sb + AS_OFF(s) + stA;
            cp_async16(a0,      gA + k0);
            cp_async16(a0 + 16, gA + k0 + 8);
            uint32_t b0 = sb + BS_OFF(s) + stA;
            cp_async16(b0,      gB + k0);
            cp_async16(b0 + 16, gB + k0 + 8);
            cp_commit();
        }
        const int s = kt & 1;
        const uint32_t As0 = sb + AS_OFF(s) + a_base;
        const uint32_t Bs0 = sb + BS_OFF(s) + b_base;
        #pragma unroll
        for (int ks = 0; ks < 2; ks++) {
            uint32_t a[4][4], b[2][4];
            #pragma unroll
            for (int mt = 0; mt < 4; mt++) ldsm_x4(a[mt], As0 + mt * 16 * 80 + ks * 32);
            #pragma unroll
            for (int pr = 0; pr < 2; pr++)  ldsm_x4(b[pr], Bs0 + pr * 16 * 80 + ks * 32);
            #pragma unroll
            for (int mt = 0; mt < 4; mt++)
                #pragma unroll
                for (int nt = 0; nt < 4; nt++)
                    mma16816(acc[mt][nt], a[mt], b[nt >> 1][(nt & 1) * 2], b[nt >> 1][(nt & 1) * 2 + 1]);
        }
    }
    __syncthreads();

    // ---- lean fused epilogue: per-row tile min + margin candidates ----
    float* sWmin = (float*)smem;                                    // 128*4 floats
    float* sMin  = (float*)(smem + 2048);                           // 128 floats
    int*   sCnt  = (int*)(smem + 2560);                             // 128 ints
    unsigned long long* sCand = (unsigned long long*)(smem + 3072); // 128*8*8B

    const float inv2 = 2.0f / ESCALE;
    float Sv[4][2], Tv[4][2];
    #pragma unroll
    for (int mt = 0; mt < 4; mt++) {
        int r0 = rowBase + warpM * 64 + mt * 16 + (lane >> 2);
        Sv[mt][0] = g_S[r0]; Sv[mt][1] = g_S[r0 + 8];
    }
    #pragma unroll
    for (int nt = 0; nt < 4; nt++) {
        int c0 = codeBase + warpN * 32 + nt * 8 + (lane & 3) * 2;
        Tv[nt][0] = g_T[c0]; Tv[nt][1] = g_T[c0 + 1];
    }

    // convert acc in place to coarse scores v = fl(S+T) - inv2*P
    #pragma unroll
    for (int mt = 0; mt < 4; mt++)
        #pragma unroll
        for (int nt = 0; nt < 4; nt++)
            #pragma unroll
            for (int half = 0; half < 2; half++)
                #pragma unroll
                for (int j = 0; j < 2; j++)
                    acc[mt][nt][half * 2 + j] =
                        __fsub_rn(__fadd_rn(Sv[mt][half], Tv[nt][j]),
                                  inv2 * acc[mt][nt][half * 2 + j]);

    // pass 1: per-row min within this warp's 32-code span (no atomics)
    #pragma unroll
    for (int mt = 0; mt < 4; mt++) {
        #pragma unroll
        for (int half = 0; half < 2; half++) {
            float mn = acc[mt][0][half * 2];
            #pragma unroll
            for (int nt = 0; nt < 4; nt++)
                #pragma unroll
                for (int j = 0; j < 2; j++)
                    mn = fminf(mn, acc[mt][nt][half * 2 + j]);
            mn = fminf(mn, __shfl_xor_sync(0xffffffffu, mn, 1));
            mn = fminf(mn, __shfl_xor_sync(0xffffffffu, mn, 2));
            if ((lane & 3) == 0) {
                int rl = warpM * 64 + mt * 16 + (lane >> 2) + half * 8;
                sWmin[(rl << 2) | warpN] = mn;
            }
        }
    }
    __syncthreads();
    if (tid < 128) {
        float m = fminf(fminf(sWmin[tid * 4], sWmin[tid * 4 + 1]),
                        fminf(sWmin[tid * 4 + 2], sWmin[tid * 4 + 3]));
        sMin[tid] = m;
        sCnt[tid] = 0;
    }
    __syncthreads();

    // pass 2: append candidates within tileMin + MARGIN
    #pragma unroll
    for (int mt = 0; mt < 4; mt++) {
        #pragma unroll
        for (int half = 0; half < 2; half++) {
            int rl = warpM * 64 + mt * 16 + (lane >> 2) + half * 8;
            float thr = sMin[rl] + MARGIN;
            #pragma unroll
            for (int nt = 0; nt < 4; nt++) {
                int c0 = warpN * 32 + nt * 8 + (lane & 3) * 2;
                #pragma unroll
                for (int j = 0; j < 2; j++) {
                    float v = acc[mt][nt][half * 2 + j];
                    if (v <= thr) {
                        int p = atomicAdd(&sCnt[rl], 1);
                        if (p < KSLOT) sCand[rl * KSLOT + p] = packvc(v, codeBase + c0 + j);
                    }
                }
            }
        }
    }
    __syncthreads();

    // write out
    if (tid < 128) {
        size_t o = (size_t)(rowBase + tid) * NTILES + tileN;
        g_tmin[o] = sMin[tid];
        g_tcnt[o] = sCnt[tid];
    }
    {
        int row = tid >> 1, h = (tid & 1) * 4;
        size_t o = ((size_t)(rowBase + row) * NTILES + tileN) * KSLOT + h;
        #pragma unroll
        for (int j = 0; j < 4; j++) g_tcand[o + j] = sCand[row * KSLOT + h + j];
    }
}

// ---------------- kernel 4: parallel candidate gather + exact fp32 rescore ---
__global__ __launch_bounds__(256, 4)
void vq_scan_kernel(const float* __restrict__ emb, float* __restrict__ out) {
    const int n = blockIdx.x;
    const int t = threadIdx.x;
    const int lane = t & 31, w = t >> 5;

    __shared__ float s_tm[NTILES];
    __shared__ int   s_tc[NTILES];
    __shared__ float s_thr;
    __shared__ int   s_cnt;
    __shared__ int   s_codes[512];
    __shared__ int   s_ovf[16];
    __shared__ int   s_novf;
    __shared__ float s_ws[8];
    __shared__ float s_bd;
    __shared__ int   s_bk;

    if (t < NTILES) {
        s_tm[t] = g_tmin[(size_t)n * NTILES + t];
        s_tc[t] = g_tcnt[(size_t)n * NTILES + t];
    }
    if (t == 0) {
        s_cnt = 0; s_novf = 0;
        s_bd = __int_as_float(0x7f800000);
        s_bk = 0x7fffffff;
    }
    __syncthreads();

    if (t < 32) {
        float m = fminf(s_tm[t], s_tm[t + 32]);
        #pragma unroll
        for (int o = 16; o; o >>= 1) m = fminf(m, __shfl_down_sync(0xffffffffu, m, o));
        if (t == 0) s_thr = m + MARGIN;
    }
    __syncthreads();
    const float thr = s_thr;

    if (t < NTILES && s_tm[t] <= thr) {
        int cnt = s_tc[t];
        if (cnt <= KSLOT) {
            size_t base = ((size_t)n * NTILES + t) * KSLOT;
            for (int c = 0; c < cnt; c++) {
                unsigned long long cd = g_tcand[base + c];
                if (unpackv(cd) <= thr) {
                    int p = atomicAdd(&s_cnt, 1);
                    if (p < 512) s_codes[p] = (int)(cd & 0xffffffffu);
                }
            }
        } else {
            int p = atomicAdd(&s_novf, 1);
            if (p < 16) s_ovf[p] = t;
        }
    }
    __syncthreads();
    {
        int novf = s_novf < 16 ? s_novf : 16;
        for (int o = 0; o < novf; o++) {
            if (t < 128) {
                int p = atomicAdd(&s_cnt, 1);
                if (p < 512) s_codes[p] = s_ovf[o] * 128 + t;
            }
        }
    }
    __syncthreads();

    const bool full = (s_cnt > 512) || (s_novf > 16);
    const int total = full ? NCODE : s_cnt;

    const float4 zv = ((const float4*)(g_zflat + (size_t)n * DIM))[t];
    const float S = g_S[n];

    for (int c = 0; c < total; c++) {
        int k = full ? c : s_codes[c];
        float4 ev = ((const float4*)(emb + (size_t)k * DIM))[t];
        float p = fmaf(zv.x, ev.x, fmaf(zv.y, ev.y, fmaf(zv.z, ev.z, zv.w * ev.w)));
        #pragma unroll
        for (int o = 16; o; o >>= 1) p += __shfl_down_sync(0xffffffffu, p, o);
        if (lane == 0) s_ws[w] = p;
        __syncthreads();
        if (t == 0) {
            float P = 0.f;
            #pragma unroll
            for (int i = 0; i < 8; i++) P += s_ws[i];
            float T = g_T[k];
            float d = __fsub_rn(__fadd_rn(S, T), 2.0f * P);
            if (d < s_bd || (d == s_bd && k < s_bk)) { s_bd = d; s_bk = k; }
        }
        __syncthreads();
    }
    if (t == 0) {
        int bk = s_bk;
        g_idx[n] = bk;
        out[OFF_IDX + n] = (float)bk;
        atomicAdd(&g_hist[bk], 1);
    }
}

// ---------------- kernel 5: gather codebook, STE output, loss ----------------
__global__ void vq_gather_kernel(const float* __restrict__ z,
                                 const float* __restrict__ emb,
                                 float* __restrict__ out) {
    int t = blockIdx.x * blockDim.x + threadIdx.x;
    int hw = t & 1023;
    int c  = (t >> 10) & 1023;
    int b  = t >> 20;
    int n  = (b << 10) | hw;
    int code = g_idx[n];
    float zv = z[t];
    float e  = emb[(size_t)code * DIM + c];
    float diff = __fsub_rn(e, zv);
    out[t] = __fadd_rn(zv, diff);
    float sq = diff * diff;
    #pragma unroll
    for (int o = 16; o; o >>= 1) sq += __shfl_down_sync(0xffffffffu, sq, o);
    __shared__ float warpsum[8];
    int lane = threadIdx.x & 31, wid = threadIdx.x >> 5;
    if (lane == 0) warpsum[wid] = sq;
    __syncthreads();
    if (wid == 0) {
        float v = (lane < 8) ? warpsum[lane] : 0.f;
        #pragma unroll
        for (int o = 4; o; o >>= 1) v += __shfl_down_sync(0xffffffffu, v, o);
        if (lane == 0) atomicAdd(&g_loss, (double)v);
    }
}

// ---------------- kernel 6: finalize loss + perplexity -----------------------
__global__ void vq_finalize_kernel(float* __restrict__ out) {
    __shared__ float warpsum[8];
    int tid = threadIdx.x;
    float s = 0.f;
    for (int k = tid; k < NCODE; k += 256) {
        float c = (float)g_hist[k];
        float p = c * (1.0f / (float)NROW);
        s += p * logf(p + 1e-10f);
    }
    #pragma unroll
    for (int o = 16; o; o >>= 1) s += __shfl_down_sync(0xffffffffu, s, o);
    int lane = tid & 31, wid = tid >> 5;
    if (lane == 0) warpsum[wid] = s;
    __syncthreads();
    if (wid == 0) {
        float v = (lane < 8) ? warpsum[lane] : 0.f;
        #pragma unroll
        for (int o = 4; o; o >>= 1) v += __shfl_down_sync(0xffffffffu, v, o);
        if (lane == 0) {
            out[OFF_PERP] = expf(-v);
            double m = g_loss / (double)ZQ_ELEMS;
            float mf = (float)m;
            out[OFF_LOSS] = __fadd_rn(mf, 0.25f * mf);
        }
    }
}

// ---------------- launch ------------------------------------------------------
extern "C" void kernel_launch(void* const* d_in, const int* in_sizes, int n_in,
                              void* d_out, int out_size) {
    const float* z   = (const float*)d_in[0];
    const float* emb = (const float*)d_in[1];
    float* out = (float*)d_out;
    (void)in_sizes; (void)n_in; (void)out_size;

    vq_zero_kernel<<<32, 256>>>();

    dim3 tb(32, 8);
    dim3 tg(32, 32, BATCH);
    vq_transpose_kernel<<<tg, tb>>>(z);

    vq_rowsum_kernel<<<(NROW + NCODE) * 32 / 256, 256>>>(emb);

    dim3 mg(NCODE / 128, NROW / 128);
    vq_mm_kernel<<<mg, 256>>>();

    vq_scan_kernel<<<NROW, 256>>>(emb, out);

    vq_gather_kernel<<<ZQ_ELEMS / 256, 256>>>(z, emb, out);

    vq_finalize_kernel<<<1, 256>>>(out);
}

// round 11
// speedup vs baseline: 3.4354x; 1.0146x over previous
#include <cuda_runtime.h>
#include <cuda_fp16.h>
#include <math.h>
#include <stdint.h>

// Problem constants
#define BATCH   8
#define DIM     1024
#define HW      1024
#define NROW    8192
#define NCODE   8192
#define ZQ_ELEMS (BATCH*DIM*HW)
#define OFF_LOSS  ZQ_ELEMS
#define OFF_PERP  (ZQ_ELEMS + 1)
#define OFF_IDX   (ZQ_ELEMS + 2)

#define ESCALE 512.0f
#define MARGIN 1e-3f
#define NTILES 64
#define KSLOT  8

// ---------------- device scratch ---------------------------------------------
__device__ float   g_zflat[(size_t)NROW * DIM];
__device__ __half  g_zh[(size_t)NROW * DIM];
__device__ __half  g_eh[(size_t)NCODE * DIM];
__device__ float   g_S[NROW];
__device__ float   g_T[NCODE];
__device__ float   g_tmin[(size_t)NROW * NTILES];
__device__ int     g_tcnt[(size_t)NROW * NTILES];
__device__ unsigned long long g_tcand[(size_t)NROW * NTILES * KSLOT];
__device__ int     g_idx[NROW];
__device__ int     g_hist[NCODE];
__device__ double  g_loss;

// ---------------- PTX helpers -------------------------------------------------
__device__ __forceinline__ uint32_t smem_u32(const void* p) {
    uint32_t a;
    asm("{ .reg .u64 t; cvta.to.shared.u64 t, %1; cvt.u32.u64 %0, t; }" : "=r"(a) : "l"(p));
    return a;
}
__device__ __forceinline__ void cp_async16(uint32_t saddr, const void* gptr) {
    asm volatile("cp.async.cg.shared.global [%0], [%1], 16;" :: "r"(saddr), "l"(gptr));
}
__device__ __forceinline__ void cp_commit() { asm volatile("cp.async.commit_group;" ::: "memory"); }
__device__ __forceinline__ void cp_wait0()  { asm volatile("cp.async.wait_group 0;" ::: "memory"); }

__device__ __forceinline__ void ldsm_x4(uint32_t* r, uint32_t addr) {
    asm volatile("ldmatrix.sync.aligned.m8n8.x4.shared.b16 {%0,%1,%2,%3}, [%4];"
                 : "=r"(r[0]), "=r"(r[1]), "=r"(r[2]), "=r"(r[3]) : "r"(addr));
}
__device__ __forceinline__ void mma16816(float* d, const uint32_t* a, uint32_t b0, uint32_t b1) {
    asm volatile("mma.sync.aligned.m16n8k16.row.col.f32.f16.f16.f32 "
                 "{%0,%1,%2,%3}, {%4,%5,%6,%7}, {%8,%9}, {%0,%1,%2,%3};"
                 : "+f"(d[0]), "+f"(d[1]), "+f"(d[2]), "+f"(d[3])
                 : "r"(a[0]), "r"(a[1]), "r"(a[2]), "r"(a[3]), "r"(b0), "r"(b1));
}
__device__ __forceinline__ unsigned long long packvc(float v, int code) {
    return ((unsigned long long)__float_as_uint(v) << 32) | (unsigned)code;
}
__device__ __forceinline__ float unpackv(unsigned long long p) {
    return __uint_as_float((unsigned)(p >> 32));
}

// ---------------- kernel 0: zero accumulators --------------------------------
__global__ void vq_zero_kernel() {
    int t = blockIdx.x * blockDim.x + threadIdx.x;
    if (t < NCODE) g_hist[t] = 0;
    if (t == 0) g_loss = 0.0;
}

// ---------------- kernel 1: transpose z -> zflat (fp32 + fp16) ---------------
__global__ void vq_transpose_kernel(const float* __restrict__ z) {
    __shared__ float tile[32][33];
    int b = blockIdx.z;
    int hw0 = blockIdx.x * 32;
    int c0  = blockIdx.y * 32;
    const float* src = z + ((size_t)b << 20);
    float* dst = g_zflat + ((size_t)b << 20);
    __half* dsth = g_zh + ((size_t)b << 20);
    #pragma unroll
    for (int r = threadIdx.y; r < 32; r += 8)
        tile[r][threadIdx.x] = src[(size_t)(c0 + r) * HW + hw0 + threadIdx.x];
    __syncthreads();
    #pragma unroll
    for (int r = threadIdx.y; r < 32; r += 8) {
        float v = tile[threadIdx.x][r];
        size_t o = (size_t)(hw0 + r) * DIM + c0 + threadIdx.x;
        dst[o]  = v;
        dsth[o] = __float2half_rn(v);
    }
}

// ---------------- kernel 2: row norms + emb fp16 (scaled) conversion ---------
__global__ void vq_rowsum_kernel(const float* __restrict__ emb) {
    int gw   = (blockIdx.x * blockDim.x + threadIdx.x) >> 5;
    int lane = threadIdx.x & 31;
    if (gw >= NROW + NCODE) return;
    const float* src;
    float* dst;
    bool isEmb = (gw >= NROW);
    if (!isEmb) { src = g_zflat + (size_t)gw * DIM; dst = g_S + gw; }
    else        { src = emb + (size_t)(gw - NROW) * DIM; dst = g_T + (gw - NROW); }
    const float4* s4 = (const float4*)src;
    __half2* eh2 = isEmb ? (__half2*)(g_eh + (size_t)(gw - NROW) * DIM) : nullptr;
    float acc = 0.f;
    #pragma unroll 4
    for (int i = lane; i < DIM / 4; i += 32) {
        float4 v = s4[i];
        if (isEmb) {
            eh2[i * 2]     = __floats2half2_rn(v.x * ESCALE, v.y * ESCALE);
            eh2[i * 2 + 1] = __floats2half2_rn(v.z * ESCALE, v.w * ESCALE);
        }
        acc += v.x * v.x + v.y * v.y + v.z * v.z + v.w * v.w;
    }
    #pragma unroll
    for (int o = 16; o; o >>= 1) acc += __shfl_down_sync(0xffffffffu, acc, o);
    if (lane == 0) *dst = acc;
}

// ---------------- kernel 3: fp16 HMMA GEMM (R10 verbatim - FROZEN) -----------
#define AS_OFF(s) ((s) * 10240u)
#define BS_OFF(s) (20480u + (s) * 10240u)

__global__ __launch_bounds__(256, 2)
void vq_mm_kernel() {
    __shared__ __align__(128) uint8_t smem[40960];
    const uint32_t sb = smem_u32(smem);
    const int tid = threadIdx.x;
    const int lane = tid & 31, wid = tid >> 5;
    const int warpM = wid >> 2, warpN = wid & 3;
    const int rowBase  = blockIdx.y * 128;
    const int codeBase = blockIdx.x * 128;
    const int tileN = blockIdx.x;

    const int ldrow = tid >> 1;
    const int ldc0  = (tid & 1) * 2;
    const __half* gA = g_zh + (size_t)(rowBase + ldrow) * DIM + ldc0 * 8;
    const __half* gB = g_eh + (size_t)(codeBase + ldrow) * DIM + ldc0 * 8;
    const uint32_t stA = (uint32_t)ldrow * 80u + (uint32_t)ldc0 * 16u;

    const uint32_t a_base = (uint32_t)((warpM * 64 + (lane & 15)) * 80 + ((lane >> 4) * 8) * 2);
    const int grp = lane >> 3;
    const uint32_t b_base = (uint32_t)((warpN * 32 + ((grp >> 1) * 8) + (lane & 7)) * 80
                                       + ((grp & 1) * 8) * 2);

    float acc[4][4][4];
    #pragma unroll
    for (int i = 0; i < 4; i++)
        #pragma unroll
        for (int j = 0; j < 4; j++)
            #pragma unroll
            for (int k = 0; k < 4; k++) acc[i][j][k] = 0.f;

    {
        uint32_t a0 = sb + AS_OFF(0) + stA;
        cp_async16(a0,      gA);
        cp_async16(a0 + 16, gA + 8);
        uint32_t b0 = sb + BS_OFF(0) + stA;
        cp_async16(b0,      gB);
        cp_async16(b0 + 16, gB + 8);
        cp_commit();
    }

    #pragma unroll 1
    for (int kt = 0; kt < 32; kt++) {
        cp_wait0();
        __syncthreads();
        if (kt < 31) {
            int k0 = (kt + 1) * 32;
            int s  = (kt + 1) & 1;
            uint32_t a0 = sb + AS_OFF(s) + stA;
            cp_async16(a0,      gA + k0);
            cp_async16(a0 + 16, gA + k0 + 8);
            uint32_t b0 = sb + BS_OFF(s) + stA;
            cp_async16(b0,      gB + k0);
            cp_async16(b0 + 16, gB + k0 + 8);
            cp_commit();
        }
        const int s = kt & 1;
        const uint32_t As0 = sb + AS_OFF(s) + a_base;
        const uint32_t Bs0 = sb + BS_OFF(s) + b_base;
        #pragma unroll
        for (int ks = 0; ks < 2; ks++) {
            uint32_t a[4][4], b[2][4];
            #pragma unroll
            for (int mt = 0; mt < 4; mt++) ldsm_x4(a[mt], As0 + mt * 16 * 80 + ks * 32);
            #pragma unroll
            for (int pr = 0; pr < 2; pr++)  ldsm_x4(b[pr], Bs0 + pr * 16 * 80 + ks * 32);
            #pragma unroll
            for (int mt = 0; mt < 4; mt++)
                #pragma unroll
                for (int nt = 0; nt < 4; nt++)
                    mma16816(acc[mt][nt], a[mt], b[nt >> 1][(nt & 1) * 2], b[nt >> 1][(nt & 1) * 2 + 1]);
        }
    }
    __syncthreads();

    // ---- lean fused epilogue: per-row tile min + margin candidates ----
    float* sWmin = (float*)smem;
    float* sMin  = (float*)(smem + 2048);
    int*   sCnt  = (int*)(smem + 2560);
    unsigned long long* sCand = (unsigned long long*)(smem + 3072);

    const float inv2 = 2.0f / ESCALE;
    float Sv[4][2], Tv[4][2];
    #pragma unroll
    for (int mt = 0; mt < 4; mt++) {
        int r0 = rowBase + warpM * 64 + mt * 16 + (lane >> 2);
        Sv[mt][0] = g_S[r0]; Sv[mt][1] = g_S[r0 + 8];
    }
    #pragma unroll
    for (int nt = 0; nt < 4; nt++) {
        int c0 = codeBase + warpN * 32 + nt * 8 + (lane & 3) * 2;
        Tv[nt][0] = g_T[c0]; Tv[nt][1] = g_T[c0 + 1];
    }

    #pragma unroll
    for (int mt = 0; mt < 4; mt++)
        #pragma unroll
        for (int nt = 0; nt < 4; nt++)
            #pragma unroll
            for (int half = 0; half < 2; half++)
                #pragma unroll
                for (int j = 0; j < 2; j++)
                    acc[mt][nt][half * 2 + j] =
                        __fsub_rn(__fadd_rn(Sv[mt][half], Tv[nt][j]),
                                  inv2 * acc[mt][nt][half * 2 + j]);

    #pragma unroll
    for (int mt = 0; mt < 4; mt++) {
        #pragma unroll
        for (int half = 0; half < 2; half++) {
            float mn = acc[mt][0][half * 2];
            #pragma unroll
            for (int nt = 0; nt < 4; nt++)
                #pragma unroll
                for (int j = 0; j < 2; j++)
                    mn = fminf(mn, acc[mt][nt][half * 2 + j]);
            mn = fminf(mn, __shfl_xor_sync(0xffffffffu, mn, 1));
            mn = fminf(mn, __shfl_xor_sync(0xffffffffu, mn, 2));
            if ((lane & 3) == 0) {
                int rl = warpM * 64 + mt * 16 + (lane >> 2) + half * 8;
                sWmin[(rl << 2) | warpN] = mn;
            }
        }
    }
    __syncthreads();
    if (tid < 128) {
        float m = fminf(fminf(sWmin[tid * 4], sWmin[tid * 4 + 1]),
                        fminf(sWmin[tid * 4 + 2], sWmin[tid * 4 + 3]));
        sMin[tid] = m;
        sCnt[tid] = 0;
    }
    __syncthreads();

    #pragma unroll
    for (int mt = 0; mt < 4; mt++) {
        #pragma unroll
        for (int half = 0; half < 2; half++) {
            int rl = warpM * 64 + mt * 16 + (lane >> 2) + half * 8;
            float thr = sMin[rl] + MARGIN;
            #pragma unroll
            for (int nt = 0; nt < 4; nt++) {
                int c0 = warpN * 32 + nt * 8 + (lane & 3) * 2;
                #pragma unroll
                for (int j = 0; j < 2; j++) {
                    float v = acc[mt][nt][half * 2 + j];
                    if (v <= thr) {
                        int p = atomicAdd(&sCnt[rl], 1);
                        if (p < KSLOT) sCand[rl * KSLOT + p] = packvc(v, codeBase + c0 + j);
                    }
                }
            }
        }
    }
    __syncthreads();

    if (tid < 128) {
        size_t o = (size_t)(rowBase + tid) * NTILES + tileN;
        g_tmin[o] = sMin[tid];
        g_tcnt[o] = sCnt[tid];
    }
    {
        int row = tid >> 1, h = (tid & 1) * 4;
        size_t o = ((size_t)(rowBase + row) * NTILES + tileN) * KSLOT + h;
        #pragma unroll
        for (int j = 0; j < 4; j++) g_tcand[o + j] = sCand[row * KSLOT + h + j];
    }
}

// ---------------- kernel 4: candidate gather + exact fp32 rescore ------------
// Same math/order as R10 (idx bit-exact); adds T-preload to smem and emb-row
// prefetch to hide the per-candidate global-load latency.
__global__ __launch_bounds__(256, 4)
void vq_scan_kernel(const float* __restrict__ emb, float* __restrict__ out) {
    const int n = blockIdx.x;
    const int t = threadIdx.x;
    const int lane = t & 31, w = t >> 5;

    __shared__ float s_tm[NTILES];
    __shared__ int   s_tc[NTILES];
    __shared__ float s_thr;
    __shared__ int   s_cnt;
    __shared__ int   s_codes[512];
    __shared__ float s_tvals[512];
    __shared__ int   s_ovf[16];
    __shared__ int   s_novf;
    __shared__ float s_ws[8];
    __shared__ float s_bd;
    __shared__ int   s_bk;

    if (t < NTILES) {
        s_tm[t] = g_tmin[(size_t)n * NTILES + t];
        s_tc[t] = g_tcnt[(size_t)n * NTILES + t];
    }
    if (t == 0) {
        s_cnt = 0; s_novf = 0;
        s_bd = __int_as_float(0x7f800000);
        s_bk = 0x7fffffff;
    }
    __syncthreads();

    if (t < 32) {
        float m = fminf(s_tm[t], s_tm[t + 32]);
        #pragma unroll
        for (int o = 16; o; o >>= 1) m = fminf(m, __shfl_down_sync(0xffffffffu, m, o));
        if (t == 0) s_thr = m + MARGIN;
    }
    __syncthreads();
    const float thr = s_thr;

    if (t < NTILES && s_tm[t] <= thr) {
        int cnt = s_tc[t];
        if (cnt <= KSLOT) {
            size_t base = ((size_t)n * NTILES + t) * KSLOT;
            for (int c = 0; c < cnt; c++) {
                unsigned long long cd = g_tcand[base + c];
                if (unpackv(cd) <= thr) {
                    int p = atomicAdd(&s_cnt, 1);
                    if (p < 512) {
                        int code = (int)(cd & 0xffffffffu);
                        s_codes[p] = code;
                        s_tvals[p] = g_T[code];
                    }
                }
            }
        } else {
            int p = atomicAdd(&s_novf, 1);
            if (p < 16) s_ovf[p] = t;
        }
    }
    __syncthreads();
    {
        int novf = s_novf < 16 ? s_novf : 16;
        for (int o = 0; o < novf; o++) {
            if (t < 128) {
                int p = atomicAdd(&s_cnt, 1);
                if (p < 512) {
                    int code = s_ovf[o] * 128 + t;
                    s_codes[p] = code;
                    s_tvals[p] = g_T[code];
                }
            }
        }
    }
    __syncthreads();

    const bool full = (s_cnt > 512) || (s_novf > 16);
    const int total = full ? NCODE : s_cnt;

    const float4 zv = ((const float4*)(g_zflat + (size_t)n * DIM))[t];
    const float S = g_S[n];

    // prefetch candidate 0's emb row
    int k = full ? 0 : s_codes[0];
    float4 ev = ((const float4*)(emb + (size_t)k * DIM))[t];

    for (int c = 0; c < total; c++) {
        // prefetch next candidate's row before reducing the current one
        int kn = k;
        float4 evn = ev;
        if (c + 1 < total) {
            kn = full ? (c + 1) : s_codes[c + 1];
            evn = ((const float4*)(emb + (size_t)kn * DIM))[t];
        }
        float p = fmaf(zv.x, ev.x, fmaf(zv.y, ev.y, fmaf(zv.z, ev.z, zv.w * ev.w)));
        #pragma unroll
        for (int o = 16; o; o >>= 1) p += __shfl_down_sync(0xffffffffu, p, o);
        if (lane == 0) s_ws[w] = p;
        __syncthreads();
        if (t == 0) {
            float P = 0.f;
            #pragma unroll
            for (int i = 0; i < 8; i++) P += s_ws[i];
            float T = full ? g_T[k] : s_tvals[c];
            float d = __fsub_rn(__fadd_rn(S, T), 2.0f * P);
            if (d < s_bd || (d == s_bd && k < s_bk)) { s_bd = d; s_bk = k; }
        }
        __syncthreads();
        k = kn;
        ev = evn;
    }
    if (t == 0) {
        int bk = s_bk;
        g_idx[n] = bk;
        out[OFF_IDX + n] = (float)bk;
        atomicAdd(&g_hist[bk], 1);
    }
}

// ---------------- kernel 5: gather codebook, STE output, loss (float4) ------
__global__ void vq_gather_kernel(const float* __restrict__ z,
                                 const float* __restrict__ emb,
                                 float* __restrict__ out) {
    int t4 = blockIdx.x * blockDim.x + threadIdx.x;   // one float4 per thread
    int base = t4 * 4;                                // (b, c, hw) layout
    int hw0 = base & 1023;
    int c   = (base >> 10) & 1023;
    int b   = base >> 20;

    float4 zv = *(const float4*)(z + base);
    float4 ov;
    float sq = 0.f;
    {
        int n = (b << 10) | hw0;
        int code = g_idx[n];
        float diff = __fsub_rn(emb[(size_t)code * DIM + c], zv.x);
        ov.x = __fadd_rn(zv.x, diff); sq = fmaf(diff, diff, sq);
    }
    {
        int n = (b << 10) | (hw0 + 1);
        int code = g_idx[n];
        float diff = __fsub_rn(emb[(size_t)code * DIM + c], zv.y);
        ov.y = __fadd_rn(zv.y, diff); sq = fmaf(diff, diff, sq);
    }
    {
        int n = (b << 10) | (hw0 + 2);
        int code = g_idx[n];
        float diff = __fsub_rn(emb[(size_t)code * DIM + c], zv.z);
        ov.z = __fadd_rn(zv.z, diff); sq = fmaf(diff, diff, sq);
    }
    {
        int n = (b << 10) | (hw0 + 3);
        int code = g_idx[n];
        float diff = __fsub_rn(emb[(size_t)code * DIM + c], zv.w);
        ov.w = __fadd_rn(zv.w, diff); sq = fmaf(diff, diff, sq);
    }
    *(float4*)(out + base) = ov;

    #pragma unroll
    for (int o = 16; o; o >>= 1) sq += __shfl_down_sync(0xffffffffu, sq, o);
    __shared__ float warpsum[8];
    int lane = threadIdx.x & 31, wid = threadIdx.x >> 5;
    if (lane == 0) warpsum[wid] = sq;
    __syncthreads();
    if (wid == 0) {
        float v = (lane < 8) ? warpsum[lane] : 0.f;
        #pragma unroll
        for (int o = 4; o; o >>= 1) v += __shfl_down_sync(0xffffffffu, v, o);
        if (lane == 0) atomicAdd(&g_loss, (double)v);
    }
}

// ---------------- kernel 6: finalize loss + perplexity -----------------------
__global__ void vq_finalize_kernel(float* __restrict__ out) {
    __shared__ float warpsum[8];
    int tid = threadIdx.x;
    float s = 0.f;
    for (int k = tid; k < NCODE; k += 256) {
        float c = (float)g_hist[k];
        float p = c * (1.0f / (float)NROW);
        s += p * logf(p + 1e-10f);
    }
    #pragma unroll
    for (int o = 16; o; o >>= 1) s += __shfl_down_sync(0xffffffffu, s, o);
    int lane = tid & 31, wid = tid >> 5;
    if (lane == 0) warpsum[wid] = s;
    __syncthreads();
    if (wid == 0) {
        float v = (lane < 8) ? warpsum[lane] : 0.f;
        #pragma unroll
        for (int o = 4; o; o >>= 1) v += __shfl_down_sync(0xffffffffu, v, o);
        if (lane == 0) {
            out[OFF_PERP] = expf(-v);
            double m = g_loss / (double)ZQ_ELEMS;
            float mf = (float)m;
            out[OFF_LOSS] = __fadd_rn(mf, 0.25f * mf);
        }
    }
}

// ---------------- launch ------------------------------------------------------
extern "C" void kernel_launch(void* const* d_in, const int* in_sizes, int n_in,
                              void* d_out, int out_size) {
    const float* z   = (const float*)d_in[0];
    const float* emb = (const float*)d_in[1];
    float* out = (float*)d_out;
    (void)in_sizes; (void)n_in; (void)out_size;

    vq_zero_kernel<<<32, 256>>>();

    dim3 tb(32, 8);
    dim3 tg(32, 32, BATCH);
    vq_transpose_kernel<<<tg, tb>>>(z);

    vq_rowsum_kernel<<<(NROW + NCODE) * 32 / 256, 256>>>(emb);

    dim3 mg(NCODE / 128, NROW / 128);
    vq_mm_kernel<<<mg, 256>>>();

    vq_scan_kernel<<<NROW, 256>>>(emb, out);

    vq_gather_kernel<<<ZQ_ELEMS / 4 / 256, 256>>>(z, emb, out);

    vq_finalize_kernel<<<1, 256>>>(out);
}